// round 8
// baseline (speedup 1.0000x reference)
#include <cuda_runtime.h>

// ---------------------------------------------------------------------------
// MiniMax-M1 lightning attention, fp32 baseline for GB300 (sm_103a).
// Pipeline: qkv GEMM+silu -> blockwise linear attention (S, scan, out) ->
//           rmsnorm*gate -> out GEMM.
// ---------------------------------------------------------------------------

#define B_    2
#define H_    16
#define N_    4096
#define DH    128
#define NB    16        // seq blocks per (b,h)
#define BLK   256       // rows per block
#define HID   2048
#define MROWS (B_*N_)   // 8192
#define NQKV  (3*H_*DH) // 6144

// Scratch (device globals; no runtime allocation allowed).
__device__ float g_q   [(size_t)B_*H_*N_*DH];
__device__ float g_k   [(size_t)B_*H_*N_*DH];
__device__ float g_v   [(size_t)B_*H_*N_*DH];
__device__ float g_attn[(size_t)MROWS*HID];   // attn out, then gated (in-place)
__device__ float g_gate[(size_t)MROWS*HID];
__device__ float g_S   [(size_t)B_*H_*NB*DH*DH];
__device__ float g_KV  [(size_t)B_*H_*NB*DH*DH];

// ---------------------------------------------------------------------------
// SGEMM  C = act(A @ B^T).  A: MxK row-major, B: NxK row-major.
// Tile 128x128, BK=16, 256 threads, 8x8 micro-tile (split 4+4 layout).
// EPI: 0 = silu -> scatter to q/k/v   1 = sigmoid -> g_gate   2 = plain -> Cout
//      (EPI==2 reads A from g_attn)
// ---------------------------------------------------------------------------
template <int EPI>
__global__ __launch_bounds__(256, 2)
void sgemm_nt(const float* __restrict__ A, const float* __restrict__ Bm,
              float* __restrict__ Cout, int K)
{
    __shared__ float As[16 * 132];
    __shared__ float Bs[16 * 132];

    const int tid = threadIdx.x;
    const int tx = tid & 15, ty = tid >> 4;
    const int bm = blockIdx.y * 128;
    const int bn = blockIdx.x * 128;

    const float* Ause = (EPI == 2) ? g_attn : A;
    const float* Ab = Ause + (size_t)bm * K;
    const float* Bb = Bm   + (size_t)bn * K;

    float acc[8][8];
#pragma unroll
    for (int i = 0; i < 8; i++)
#pragma unroll
        for (int j = 0; j < 8; j++) acc[i][j] = 0.f;

    for (int k0 = 0; k0 < K; k0 += 16) {
#pragma unroll
        for (int p = 0; p < 2; p++) {
            int idx = tid + p * 256;         // 0..511
            int row = idx >> 2;              // 0..127
            int kq  = (idx & 3) * 4;         // 0,4,8,12
            float4 va = *(const float4*)(Ab + (size_t)row * K + k0 + kq);
            As[(kq + 0) * 132 + row] = va.x;
            As[(kq + 1) * 132 + row] = va.y;
            As[(kq + 2) * 132 + row] = va.z;
            As[(kq + 3) * 132 + row] = va.w;
            float4 vb = *(const float4*)(Bb + (size_t)row * K + k0 + kq);
            Bs[(kq + 0) * 132 + row] = vb.x;
            Bs[(kq + 1) * 132 + row] = vb.y;
            Bs[(kq + 2) * 132 + row] = vb.z;
            Bs[(kq + 3) * 132 + row] = vb.w;
        }
        __syncthreads();
#pragma unroll
        for (int kk = 0; kk < 16; kk++) {
            float a[8], b[8];
            *(float4*)(a)     = *(const float4*)&As[kk * 132 + ty * 4];
            *(float4*)(a + 4) = *(const float4*)&As[kk * 132 + 64 + ty * 4];
            *(float4*)(b)     = *(const float4*)&Bs[kk * 132 + tx * 4];
            *(float4*)(b + 4) = *(const float4*)&Bs[kk * 132 + 64 + tx * 4];
#pragma unroll
            for (int i = 0; i < 8; i++)
#pragma unroll
                for (int j = 0; j < 8; j++)
                    acc[i][j] += a[i] * b[j];
        }
        __syncthreads();
    }

    // epilogue
#pragma unroll
    for (int i = 0; i < 8; i++) {
        int mloc = (i < 4) ? (ty * 4 + i) : (64 + ty * 4 + i - 4);
        int m = bm + mloc;
#pragma unroll
        for (int j = 0; j < 8; j++) {
            int nloc = (j < 4) ? (tx * 4 + j) : (64 + tx * 4 + j - 4);
            int nn = bn + nloc;
            float v = acc[i][j];
            if (EPI == 0) {
                float sv = v / (1.f + __expf(-v));       // silu
                int s    = nn >> 11;                     // 0,1,2 (q,k,v)
                int rem  = nn & 2047;
                int head = rem >> 7;
                int d    = rem & 127;
                int b    = m >> 12;
                int t    = m & 4095;
                float* dst = (s == 0) ? g_q : (s == 1) ? g_k : g_v;
                dst[(((size_t)(b * H_ + head)) * N_ + t) * DH + d] = sv;
            } else if (EPI == 1) {
                g_gate[(size_t)m * HID + nn] = 1.f / (1.f + __expf(-v));
            } else {
                Cout[(size_t)m * HID + nn] = v;
            }
        }
    }
}

// ---------------------------------------------------------------------------
// A1: per (bh, blk) compute S[d][e] = sum_r k[r][d]*exp(-s*(255-r))*v[r][e]
// 128x128 output, contraction 256, 4 chunks of 64 rows.
// ---------------------------------------------------------------------------
__global__ __launch_bounds__(256)
void attn_S(const float* __restrict__ slope)
{
    extern __shared__ float sm[];
    float* ks = sm;               // [64][132]
    float* vs = sm + 64 * 132;    // [64][132]

    const int blk = blockIdx.x;
    const int bh  = blockIdx.y;
    const float s = slope[bh & (H_ - 1)];
    const float* kp = g_k + ((size_t)bh * N_ + blk * BLK) * DH;
    const float* vp = g_v + ((size_t)bh * N_ + blk * BLK) * DH;
    const int tid = threadIdx.x, tx = tid & 15, ty = tid >> 4;

    float acc[8][8];
#pragma unroll
    for (int i = 0; i < 8; i++)
#pragma unroll
        for (int j = 0; j < 8; j++) acc[i][j] = 0.f;

    for (int c = 0; c < 4; c++) {
#pragma unroll
        for (int p = 0; p < 8; p++) {
            int idx = tid + p * 256;       // 0..2047
            int r   = idx >> 5;            // 0..63
            int d   = (idx & 31) * 4;
            int rg  = c * 64 + r;
            float kd = __expf(-s * (float)(255 - rg));
            float4 k4 = *(const float4*)(kp + (size_t)rg * DH + d);
            ks[r * 132 + d + 0] = k4.x * kd;
            ks[r * 132 + d + 1] = k4.y * kd;
            ks[r * 132 + d + 2] = k4.z * kd;
            ks[r * 132 + d + 3] = k4.w * kd;
            float4 v4 = *(const float4*)(vp + (size_t)rg * DH + d);
            *(float4*)&vs[r * 132 + d] = v4;
        }
        __syncthreads();
        for (int r = 0; r < 64; r++) {
            float a[8], b[8];
            *(float4*)(a)     = *(const float4*)&ks[r * 132 + ty * 4];
            *(float4*)(a + 4) = *(const float4*)&ks[r * 132 + 64 + ty * 4];
            *(float4*)(b)     = *(const float4*)&vs[r * 132 + tx * 4];
            *(float4*)(b + 4) = *(const float4*)&vs[r * 132 + 64 + tx * 4];
#pragma unroll
            for (int i = 0; i < 8; i++)
#pragma unroll
                for (int j = 0; j < 8; j++)
                    acc[i][j] += a[i] * b[j];
        }
        __syncthreads();
    }

    float* Sp = g_S + (size_t)(bh * NB + blk) * DH * DH;
#pragma unroll
    for (int i = 0; i < 8; i++) {
        int d = (i < 4) ? (ty * 4 + i) : (64 + ty * 4 + i - 4);
#pragma unroll
        for (int j = 0; j < 8; j++) {
            int e = (j < 4) ? (tx * 4 + j) : (64 + tx * 4 + j - 4);
            Sp[d * DH + e] = acc[i][j];
        }
    }
}

// ---------------------------------------------------------------------------
// A2: per-bh scan of KV states:  KV[j] = bdec*KV[j-1] + S[j-1], KV[0] = 0.
// ---------------------------------------------------------------------------
__global__ __launch_bounds__(256)
void attn_scan(const float* __restrict__ slope)
{
    int bh = blockIdx.x;
    float bdec = __expf(-slope[bh & (H_ - 1)] * (float)BLK);
    const float* Sp  = g_S  + (size_t)bh * NB * DH * DH;
    float*       KVp = g_KV + (size_t)bh * NB * DH * DH;
    for (int idx = threadIdx.x; idx < DH * DH; idx += blockDim.x) {
        float kv = 0.f;
#pragma unroll
        for (int j = 0; j < NB; j++) {
            KVp[(size_t)j * DH * DH + idx] = kv;
            kv = bdec * kv + Sp[(size_t)j * DH * DH + idx];
        }
    }
}

// ---------------------------------------------------------------------------
// A3: per (bh, blk) fused output:
//   out[m][e] = qdecay[m] * sum_d q[m][d]*KV[d][e]
//             + sum_{k<=m} exp(-s*(m-k)) * (q[m]·k[k]) * v[k][e]
// m-tiles of 64 rows; causal k-tiles (kt<=mt only).
// ---------------------------------------------------------------------------
#define A3_SMEM_FLOATS (128*65 + (128*65 + 64*65 + 64*132))
__global__ __launch_bounds__(256)
void attn_out(const float* __restrict__ slope)
{
    extern __shared__ float sm[];
    float* qT  = sm;                       // [128][65]  qT[d*65+m]
    float* un  = sm + 128 * 65;            // union region
    float* kT  = un;                       // [128][65]  kT[d*65+k]
    float* Ps  = un + 128 * 65;            // [64][65]
    float* vsm = Ps + 64 * 65;             // [64][132]
    float* kvs = un;                       // [128][132] (aliases kT/Ps/vsm)

    const int blk = blockIdx.x;
    const int bh  = blockIdx.y;
    const float s = slope[bh & (H_ - 1)];
    const int tid = threadIdx.x, tx = tid & 15, ty = tid >> 4;

    const float* qp  = g_q  + ((size_t)bh * N_ + blk * BLK) * DH;
    const float* kp  = g_k  + ((size_t)bh * N_ + blk * BLK) * DH;
    const float* vp  = g_v  + ((size_t)bh * N_ + blk * BLK) * DH;
    const float* kvp = g_KV + (size_t)(bh * NB + blk) * DH * DH;
    const int b = bh >> 4, h = bh & (H_ - 1);
    float* outp = g_attn + ((size_t)b * N_ + blk * BLK) * HID + h * DH;

    for (int mt = 0; mt < 4; mt++) {
        const int m0 = mt * 64;
        // stage qT (64 rows transposed) and kvs [128][132]
#pragma unroll
        for (int p = 0; p < 8; p++) {
            int idx = tid + p * 256;
            int r = idx >> 5;              // 0..63
            int d = (idx & 31) * 4;
            float4 q4 = *(const float4*)(qp + (size_t)(m0 + r) * DH + d);
            qT[(d + 0) * 65 + r] = q4.x;
            qT[(d + 1) * 65 + r] = q4.y;
            qT[(d + 2) * 65 + r] = q4.z;
            qT[(d + 3) * 65 + r] = q4.w;
        }
#pragma unroll
        for (int p = 0; p < 16; p++) {
            int idx = tid + p * 256;       // 0..4095
            int r = idx >> 5;              // d-row 0..127
            int e = (idx & 31) * 4;
            *(float4*)&kvs[r * 132 + e] = *(const float4*)(kvp + (size_t)r * DH + e);
        }
        __syncthreads();

        // inter: out = q @ KV (raw), then scale rows by qdecay
        float out[4][8];
#pragma unroll
        for (int i = 0; i < 4; i++)
#pragma unroll
            for (int j = 0; j < 8; j++) out[i][j] = 0.f;

        for (int d = 0; d < 128; d++) {
            float a[4];
#pragma unroll
            for (int i = 0; i < 4; i++) a[i] = qT[d * 65 + ty * 4 + i];
            float b0[4], b1[4];
            *(float4*)b0 = *(const float4*)&kvs[d * 132 + tx * 4];
            *(float4*)b1 = *(const float4*)&kvs[d * 132 + 64 + tx * 4];
#pragma unroll
            for (int i = 0; i < 4; i++) {
#pragma unroll
                for (int j = 0; j < 4; j++) {
                    out[i][j]     += a[i] * b0[j];
                    out[i][j + 4] += a[i] * b1[j];
                }
            }
        }
#pragma unroll
        for (int i = 0; i < 4; i++) {
            float qd = __expf(-s * (float)(m0 + ty * 4 + i + 1));
#pragma unroll
            for (int j = 0; j < 8; j++) out[i][j] *= qd;
        }
        __syncthreads();   // done reading kvs before union reuse

        // intra: causal k-tiles
        for (int kt = 0; kt <= mt; kt++) {
#pragma unroll
            for (int p = 0; p < 8; p++) {
                int idx = tid + p * 256;
                int r = idx >> 5;
                int d = (idx & 31) * 4;
                float4 k4 = *(const float4*)(kp + (size_t)(kt * 64 + r) * DH + d);
                kT[(d + 0) * 65 + r] = k4.x;
                kT[(d + 1) * 65 + r] = k4.y;
                kT[(d + 2) * 65 + r] = k4.z;
                kT[(d + 3) * 65 + r] = k4.w;
                float4 v4 = *(const float4*)(vp + (size_t)(kt * 64 + r) * DH + d);
                *(float4*)&vsm[r * 132 + d] = v4;
            }
            __syncthreads();

            // P[m][k] = q_m . k_k   (64x64, 4x4 micro)
            float P[4][4];
#pragma unroll
            for (int i = 0; i < 4; i++)
#pragma unroll
                for (int j = 0; j < 4; j++) P[i][j] = 0.f;
            for (int d = 0; d < 128; d++) {
                float a[4], c[4];
#pragma unroll
                for (int i = 0; i < 4; i++) a[i] = qT[d * 65 + ty * 4 + i];
#pragma unroll
                for (int j = 0; j < 4; j++) c[j] = kT[d * 65 + tx * 4 + j];
#pragma unroll
                for (int i = 0; i < 4; i++)
#pragma unroll
                    for (int j = 0; j < 4; j++)
                        P[i][j] += a[i] * c[j];
            }
            // causal decay, store to smem
#pragma unroll
            for (int i = 0; i < 4; i++) {
                int m = m0 + ty * 4 + i;
#pragma unroll
                for (int j = 0; j < 4; j++) {
                    int kk = kt * 64 + tx * 4 + j;
                    float w = (m >= kk) ? __expf(-s * (float)(m - kk)) : 0.f;
                    Ps[(ty * 4 + i) * 65 + tx * 4 + j] = P[i][j] * w;
                }
            }
            __syncthreads();
            // out += Ps @ v   (contraction 64)
            for (int r = 0; r < 64; r++) {
                float a[4];
#pragma unroll
                for (int i = 0; i < 4; i++) a[i] = Ps[(ty * 4 + i) * 65 + r];
                float b0[4], b1[4];
                *(float4*)b0 = *(const float4*)&vsm[r * 132 + tx * 4];
                *(float4*)b1 = *(const float4*)&vsm[r * 132 + 64 + tx * 4];
#pragma unroll
                for (int i = 0; i < 4; i++) {
#pragma unroll
                    for (int j = 0; j < 4; j++) {
                        out[i][j]     += a[i] * b0[j];
                        out[i][j + 4] += a[i] * b1[j];
                    }
                }
            }
            __syncthreads();
        }

        // write out tile
#pragma unroll
        for (int i = 0; i < 4; i++) {
            int m = m0 + ty * 4 + i;
#pragma unroll
            for (int j = 0; j < 8; j++) {
                int e = (j < 4) ? (tx * 4 + j) : (64 + tx * 4 + j - 4);
                outp[(size_t)m * HID + e] = out[i][j];
            }
        }
        __syncthreads();
    }
}

// ---------------------------------------------------------------------------
// K4: rmsnorm over HID per token, multiply by gate and norm_w, in-place.
// ---------------------------------------------------------------------------
__global__ __launch_bounds__(256)
void rms_gate(const float* __restrict__ norm_w)
{
    const int row = blockIdx.x;
    float* x        = g_attn + (size_t)row * HID;
    const float* gt = g_gate + (size_t)row * HID;

    float xv[8];
    float ss = 0.f;
#pragma unroll
    for (int p = 0; p < 8; p++) {
        xv[p] = x[threadIdx.x + p * 256];
        ss += xv[p] * xv[p];
    }
    __shared__ float red[8];
#pragma unroll
    for (int o = 16; o > 0; o >>= 1)
        ss += __shfl_xor_sync(0xffffffffu, ss, o);
    if ((threadIdx.x & 31) == 0) red[threadIdx.x >> 5] = ss;
    __syncthreads();
    float tot = 0.f;
#pragma unroll
    for (int w = 0; w < 8; w++) tot += red[w];
    float inv = rsqrtf(tot / (float)HID + 1e-6f);
#pragma unroll
    for (int p = 0; p < 8; p++) {
        int i = threadIdx.x + p * 256;
        x[i] = gt[i] * xv[p] * inv * norm_w[i];
    }
}

// ---------------------------------------------------------------------------
extern "C" void kernel_launch(void* const* d_in, const int* in_sizes, int n_in,
                              void* d_out, int out_size)
{
    const float* hidden = (const float*)d_in[0];
    const float* slope  = (const float*)d_in[1];
    const float* w_qkv  = (const float*)d_in[2];
    const float* w_gate = (const float*)d_in[3];
    const float* w_out  = (const float*)d_in[4];
    const float* norm_w = (const float*)d_in[5];
    float* out = (float*)d_out;

    cudaFuncSetAttribute(attn_S,  cudaFuncAttributeMaxDynamicSharedMemorySize,
                         2 * 64 * 132 * (int)sizeof(float));
    cudaFuncSetAttribute(attn_out, cudaFuncAttributeMaxDynamicSharedMemorySize,
                         A3_SMEM_FLOATS * (int)sizeof(float));

    // 1) qkv = silu(hidden @ w_qkv^T) -> q,k,v (b,h,n,d)
    sgemm_nt<0><<<dim3(NQKV / 128, MROWS / 128), 256>>>(hidden, w_qkv, nullptr, HID);
    // 2) gate = sigmoid(hidden @ w_gate^T)
    sgemm_nt<1><<<dim3(HID / 128, MROWS / 128), 256>>>(hidden, w_gate, nullptr, HID);
    // 3) attention
    attn_S  <<<dim3(NB, B_ * H_), 256, 2 * 64 * 132 * sizeof(float)>>>(slope);
    attn_scan<<<B_ * H_, 256>>>(slope);
    attn_out<<<dim3(NB, B_ * H_), 256, A3_SMEM_FLOATS * sizeof(float)>>>(slope);
    // 4) rmsnorm * gate (in-place into g_attn)
    rms_gate<<<MROWS, 256>>>(norm_w);
    // 5) out = gated @ w_out^T
    sgemm_nt<2><<<dim3(HID / 128, MROWS / 128), 256>>>(nullptr, w_out, out, HID);
}

// round 10
// speedup vs baseline: 1.5725x; 1.5725x over previous
#include <cuda_runtime.h>
#include <cuda_bf16.h>
#include <mma.h>
#include <cstdint>

using namespace nvcuda;

// ---------------------------------------------------------------------------
// MiniMax-M1 lightning attention — R10: wmma(bf16-split) GEMMs + parallel scan.
// tcgen05 is unusable (harness ptxas target = plain sm_103: tcgen05.ld is
// 'a'-only). Legacy wmma/HMMA path instead. GEMM: C = A@B^T via one fused
// K'=6144 loop over parts (AhBh, AhBl, AlBh), fp32 accumulate.
// ---------------------------------------------------------------------------

#define B_    2
#define H_    16
#define N_    4096
#define DH    128
#define NB    16
#define BLK   256
#define HID   2048
#define MROWS (B_*N_)          // 8192
#define NQKV  (3*H_*DH)        // 6144
#define WROWS (NQKV+HID+HID)   // 10240
#define NCHUNK 96              // K'=6144 in 64-wide chunks

// Scratch (device globals; no runtime allocation allowed).
__device__ float g_q   [(size_t)B_*H_*N_*DH];
__device__ float g_k   [(size_t)B_*H_*N_*DH];
__device__ float g_v   [(size_t)B_*H_*N_*DH];
__device__ float g_attn[(size_t)MROWS*HID];
__device__ float g_gate[(size_t)MROWS*HID];
__device__ float g_S   [(size_t)B_*H_*NB*DH*DH];
__device__ float g_KV  [(size_t)B_*H_*NB*DH*DH];
__device__ __nv_bfloat16 g_Ah[(size_t)MROWS*HID];
__device__ __nv_bfloat16 g_Al[(size_t)MROWS*HID];
__device__ __nv_bfloat16 g_Wh[(size_t)WROWS*HID];
__device__ __nv_bfloat16 g_Wl[(size_t)WROWS*HID];

// ---------------------------------------------------------------------------
// fp32 -> (bf16 hi, bf16 lo) conversion kernels
// ---------------------------------------------------------------------------
__device__ __forceinline__ void cvt4(float4 v, __nv_bfloat162* hi2, __nv_bfloat162* lo2, size_t i) {
    __nv_bfloat16 h0 = __float2bfloat16(v.x), h1 = __float2bfloat16(v.y);
    __nv_bfloat16 h2 = __float2bfloat16(v.z), h3 = __float2bfloat16(v.w);
    __nv_bfloat16 l0 = __float2bfloat16(v.x - __bfloat162float(h0));
    __nv_bfloat16 l1 = __float2bfloat16(v.y - __bfloat162float(h1));
    __nv_bfloat16 l2 = __float2bfloat16(v.z - __bfloat162float(h2));
    __nv_bfloat16 l3 = __float2bfloat16(v.w - __bfloat162float(h3));
    hi2[i*2+0] = __nv_bfloat162(h0, h1); hi2[i*2+1] = __nv_bfloat162(h2, h3);
    lo2[i*2+0] = __nv_bfloat162(l0, l1); lo2[i*2+1] = __nv_bfloat162(l2, l3);
}
__global__ void conv_a(const float* __restrict__ src, int n4) {
    int i = blockIdx.x * 256 + threadIdx.x;
    if (i < n4) cvt4(((const float4*)src)[i], (__nv_bfloat162*)g_Ah, (__nv_bfloat162*)g_Al, i);
}
__global__ void conv_w(const float* __restrict__ src, size_t dst_off_elems, int n4) {
    int i = blockIdx.x * 256 + threadIdx.x;
    if (i < n4) cvt4(((const float4*)src)[i],
                     (__nv_bfloat162*)(g_Wh + dst_off_elems),
                     (__nv_bfloat162*)(g_Wl + dst_off_elems), i);
}
__global__ void conv_attn(int n4) {
    int i = blockIdx.x * 256 + threadIdx.x;
    if (i < n4) cvt4(((const float4*)g_attn)[i], (__nv_bfloat162*)g_Ah, (__nv_bfloat162*)g_Al, i);
}

// ---------------------------------------------------------------------------
// wmma bf16-split GEMM: C[M,N] = act(A @ B^T).
// A rows: g_Ah/g_Al [MROWS][2048]; B rows: g_Wh/g_Wl + BOFFROWS*2048.
// Tile 128x128, 256 thr (8 warps, 4x2), BK=64 bf16, double-buffered smem.
// smem per buffer: A[128][72] + B[128][72] bf16 = 36864 B; x2 = 73728.
// Epilogue stages fp32 tiles through smem (reused) for activation/scatter.
// EPI: 0 silu->q/k/v scatter, 1 sigmoid->g_gate, 2 plain->Cout.
// ---------------------------------------------------------------------------
#define ASTRIDE 72
#define ABUF_ELEMS (128*ASTRIDE)            // 9216 bf16
#define BUF_BYTES  (2*ABUF_ELEMS*2)         // 36864
#define GEMM_SMEM  (2*BUF_BYTES)            // 73728

template <int EPI, int BOFFROWS>
__global__ __launch_bounds__(256)
void gemm_wmma(float* __restrict__ Cout)
{
    extern __shared__ char smraw[];

    const int tid  = threadIdx.x;
    const int wid  = tid >> 5, lane = tid & 31;
    const int wm   = wid >> 1;          // 0..3  -> m offset 32*wm
    const int wn   = wid & 1;           // 0..1  -> n offset 64*wn
    const int bm   = blockIdx.y * 128, bn = blockIdx.x * 128;

    const __nv_bfloat16* Bh = g_Wh + (size_t)BOFFROWS * HID;
    const __nv_bfloat16* Bl = g_Wl + (size_t)BOFFROWS * HID;

    wmma::fragment<wmma::accumulator, 16, 16, 16, float> acc[2][4];
#pragma unroll
    for (int i = 0; i < 2; i++)
#pragma unroll
        for (int j = 0; j < 4; j++) wmma::fill_fragment(acc[i][j], 0.f);

    auto load_chunk = [&](int c, int buf) {
        const int part = c >> 5;                  // 0:hh 1:hl 2:lh
        const int k0 = (c & 31) << 6;
        const __nv_bfloat16* As = (part < 2) ? g_Ah : g_Al;
        const __nv_bfloat16* Bs = (part == 1) ? Bl : Bh;
        __nv_bfloat16* a = (__nv_bfloat16*)(smraw + buf * BUF_BYTES);
        __nv_bfloat16* b = a + ABUF_ELEMS;
#pragma unroll
        for (int i = 0; i < 4; i++) {
            int idx = i * 256 + tid;              // 0..1023
            int row = idx >> 3, c8 = idx & 7;     // 128 rows x 8 uint4
            *(uint4*)(a + row * ASTRIDE + c8 * 8) =
                *(const uint4*)(As + (size_t)(bm + row) * HID + k0 + c8 * 8);
            *(uint4*)(b + row * ASTRIDE + c8 * 8) =
                *(const uint4*)(Bs + (size_t)(bn + row) * HID + k0 + c8 * 8);
        }
    };
    auto compute = [&](int buf) {
        const __nv_bfloat16* a = (const __nv_bfloat16*)(smraw + buf * BUF_BYTES);
        const __nv_bfloat16* b = a + ABUF_ELEMS;
#pragma unroll
        for (int ks = 0; ks < 4; ks++) {
            wmma::fragment<wmma::matrix_a, 16, 16, 16, __nv_bfloat16, wmma::row_major> af[2];
            wmma::fragment<wmma::matrix_b, 16, 16, 16, __nv_bfloat16, wmma::col_major> bf[4];
#pragma unroll
            for (int i = 0; i < 2; i++)
                wmma::load_matrix_sync(af[i], a + (wm * 32 + i * 16) * ASTRIDE + ks * 16, ASTRIDE);
#pragma unroll
            for (int j = 0; j < 4; j++)
                wmma::load_matrix_sync(bf[j], b + (wn * 64 + j * 16) * ASTRIDE + ks * 16, ASTRIDE);
#pragma unroll
            for (int i = 0; i < 2; i++)
#pragma unroll
                for (int j = 0; j < 4; j++)
                    wmma::mma_sync(acc[i][j], af[i], bf[j], acc[i][j]);
        }
    };

    load_chunk(0, 0);
    __syncthreads();
    for (int c = 0; c < NCHUNK; c++) {
        if (c + 1 < NCHUNK) load_chunk(c + 1, (c + 1) & 1);
        compute(c & 1);
        __syncthreads();
    }

    // ---- epilogue: stage fp32 through smem (A/B buffers reused) ----
    float* stage = (float*)smraw + wid * (32 * 68);   // per-warp 32x68 region
#pragma unroll
    for (int i = 0; i < 2; i++)
#pragma unroll
        for (int j = 0; j < 4; j++)
            wmma::store_matrix_sync(stage + i * 16 * 68 + j * 16, acc[i][j], 68,
                                    wmma::mem_row_major);
    __syncwarp();

    const int mrow = bm + wm * 32 + lane;
#pragma unroll 8
    for (int c = 0; c < 64; c++) {
        float v = stage[lane * 68 + c];
        int nn = bn + wn * 64 + c;
        if (EPI == 0) {
            float sv = v / (1.f + __expf(-v));       // silu
            int s    = nn >> 11;                     // 0,1,2 = q,k,v
            int rem  = nn & 2047;
            int head = rem >> 7;
            int d    = rem & 127;
            int b    = mrow >> 12;
            int t    = mrow & 4095;
            float* dst = (s == 0) ? g_q : (s == 1) ? g_k : g_v;
            dst[(((size_t)(b * H_ + head)) * N_ + t) * DH + d] = sv;
        } else if (EPI == 1) {
            g_gate[(size_t)mrow * HID + nn] = 1.f / (1.f + __expf(-v));
        } else {
            Cout[(size_t)mrow * HID + nn] = v;
        }
    }
}

// ---------------------------------------------------------------------------
// A1: S[d][e] = sum_r k[r][d]*exp(-s*(255-r))*v[r][e]  (verified R8)
// ---------------------------------------------------------------------------
__global__ __launch_bounds__(256)
void attn_S(const float* __restrict__ slope)
{
    extern __shared__ float sm[];
    float* ks = sm;
    float* vs = sm + 64 * 132;

    const int blk = blockIdx.x;
    const int bh  = blockIdx.y;
    const float s = slope[bh & (H_ - 1)];
    const float* kp = g_k + ((size_t)bh * N_ + blk * BLK) * DH;
    const float* vp = g_v + ((size_t)bh * N_ + blk * BLK) * DH;
    const int tid = threadIdx.x, tx = tid & 15, ty = tid >> 4;

    float acc[8][8];
#pragma unroll
    for (int i = 0; i < 8; i++)
#pragma unroll
        for (int j = 0; j < 8; j++) acc[i][j] = 0.f;

    for (int c = 0; c < 4; c++) {
#pragma unroll
        for (int p = 0; p < 8; p++) {
            int idx = tid + p * 256;
            int r   = idx >> 5;
            int d   = (idx & 31) * 4;
            int rg  = c * 64 + r;
            float kd = __expf(-s * (float)(255 - rg));
            float4 k4 = *(const float4*)(kp + (size_t)rg * DH + d);
            ks[r * 132 + d + 0] = k4.x * kd;
            ks[r * 132 + d + 1] = k4.y * kd;
            ks[r * 132 + d + 2] = k4.z * kd;
            ks[r * 132 + d + 3] = k4.w * kd;
            float4 v4 = *(const float4*)(vp + (size_t)rg * DH + d);
            *(float4*)&vs[r * 132 + d] = v4;
        }
        __syncthreads();
        for (int r = 0; r < 64; r++) {
            float a[8], b[8];
            *(float4*)(a)     = *(const float4*)&ks[r * 132 + ty * 4];
            *(float4*)(a + 4) = *(const float4*)&ks[r * 132 + 64 + ty * 4];
            *(float4*)(b)     = *(const float4*)&vs[r * 132 + tx * 4];
            *(float4*)(b + 4) = *(const float4*)&vs[r * 132 + 64 + tx * 4];
#pragma unroll
            for (int i = 0; i < 8; i++)
#pragma unroll
                for (int j = 0; j < 8; j++)
                    acc[i][j] += a[i] * b[j];
        }
        __syncthreads();
    }

    float* Sp = g_S + (size_t)(bh * NB + blk) * DH * DH;
#pragma unroll
    for (int i = 0; i < 8; i++) {
        int d = (i < 4) ? (ty * 4 + i) : (64 + ty * 4 + i - 4);
#pragma unroll
        for (int j = 0; j < 8; j++) {
            int e = (j < 4) ? (tx * 4 + j) : (64 + tx * 4 + j - 4);
            Sp[d * DH + e] = acc[i][j];
        }
    }
}

// ---------------------------------------------------------------------------
// A2: parallel over bh x idx; 16-step scan per thread.
// ---------------------------------------------------------------------------
__global__ __launch_bounds__(256)
void attn_scan(const float* __restrict__ slope)
{
    int gid = blockIdx.x * 256 + threadIdx.x;
    int bh  = gid >> 14;
    int idx = gid & 16383;
    float bdec = __expf(-slope[bh & (H_ - 1)] * (float)BLK);
    const float* Sp  = g_S  + (size_t)bh * NB * DH * DH + idx;
    float*       KVp = g_KV + (size_t)bh * NB * DH * DH + idx;
    float kv = 0.f;
#pragma unroll
    for (int j = 0; j < NB; j++) {
        KVp[(size_t)j * DH * DH] = kv;
        kv = bdec * kv + Sp[(size_t)j * DH * DH];
    }
}

// ---------------------------------------------------------------------------
// A3: fused inter+intra attention output (verified R8)
// ---------------------------------------------------------------------------
#define A3_SMEM_FLOATS (128*65 + (128*65 + 64*65 + 64*132))
__global__ __launch_bounds__(256)
void attn_out(const float* __restrict__ slope)
{
    extern __shared__ float sm[];
    float* qT  = sm;
    float* un  = sm + 128 * 65;
    float* kT  = un;
    float* Ps  = un + 128 * 65;
    float* vsm = Ps + 64 * 65;
    float* kvs = un;

    const int blk = blockIdx.x;
    const int bh  = blockIdx.y;
    const float s = slope[bh & (H_ - 1)];
    const int tid = threadIdx.x, tx = tid & 15, ty = tid >> 4;

    const float* qp  = g_q  + ((size_t)bh * N_ + blk * BLK) * DH;
    const float* kp  = g_k  + ((size_t)bh * N_ + blk * BLK) * DH;
    const float* vp  = g_v  + ((size_t)bh * N_ + blk * BLK) * DH;
    const float* kvp = g_KV + (size_t)(bh * NB + blk) * DH * DH;
    const int b = bh >> 4, h = bh & (H_ - 1);
    float* outp = g_attn + ((size_t)b * N_ + blk * BLK) * HID + h * DH;

    for (int mt = 0; mt < 4; mt++) {
        const int m0 = mt * 64;
#pragma unroll
        for (int p = 0; p < 8; p++) {
            int idx = tid + p * 256;
            int r = idx >> 5;
            int d = (idx & 31) * 4;
            float4 q4 = *(const float4*)(qp + (size_t)(m0 + r) * DH + d);
            qT[(d + 0) * 65 + r] = q4.x;
            qT[(d + 1) * 65 + r] = q4.y;
            qT[(d + 2) * 65 + r] = q4.z;
            qT[(d + 3) * 65 + r] = q4.w;
        }
#pragma unroll
        for (int p = 0; p < 16; p++) {
            int idx = tid + p * 256;
            int r = idx >> 5;
            int e = (idx & 31) * 4;
            *(float4*)&kvs[r * 132 + e] = *(const float4*)(kvp + (size_t)r * DH + e);
        }
        __syncthreads();

        float out[4][8];
#pragma unroll
        for (int i = 0; i < 4; i++)
#pragma unroll
            for (int j = 0; j < 8; j++) out[i][j] = 0.f;

        for (int d = 0; d < 128; d++) {
            float a[4];
#pragma unroll
            for (int i = 0; i < 4; i++) a[i] = qT[d * 65 + ty * 4 + i];
            float b0[4], b1[4];
            *(float4*)b0 = *(const float4*)&kvs[d * 132 + tx * 4];
            *(float4*)b1 = *(const float4*)&kvs[d * 132 + 64 + tx * 4];
#pragma unroll
            for (int i = 0; i < 4; i++) {
#pragma unroll
                for (int j = 0; j < 4; j++) {
                    out[i][j]     += a[i] * b0[j];
                    out[i][j + 4] += a[i] * b1[j];
                }
            }
        }
#pragma unroll
        for (int i = 0; i < 4; i++) {
            float qd = __expf(-s * (float)(m0 + ty * 4 + i + 1));
#pragma unroll
            for (int j = 0; j < 8; j++) out[i][j] *= qd;
        }
        __syncthreads();

        for (int kt = 0; kt <= mt; kt++) {
#pragma unroll
            for (int p = 0; p < 8; p++) {
                int idx = tid + p * 256;
                int r = idx >> 5;
                int d = (idx & 31) * 4;
                float4 k4 = *(const float4*)(kp + (size_t)(kt * 64 + r) * DH + d);
                kT[(d + 0) * 65 + r] = k4.x;
                kT[(d + 1) * 65 + r] = k4.y;
                kT[(d + 2) * 65 + r] = k4.z;
                kT[(d + 3) * 65 + r] = k4.w;
                float4 v4 = *(const float4*)(vp + (size_t)(kt * 64 + r) * DH + d);
                *(float4*)&vsm[r * 132 + d] = v4;
            }
            __syncthreads();

            float P[4][4];
#pragma unroll
            for (int i = 0; i < 4; i++)
#pragma unroll
                for (int j = 0; j < 4; j++) P[i][j] = 0.f;
            for (int d = 0; d < 128; d++) {
                float a[4], c[4];
#pragma unroll
                for (int i = 0; i < 4; i++) a[i] = qT[d * 65 + ty * 4 + i];
#pragma unroll
                for (int j = 0; j < 4; j++) c[j] = kT[d * 65 + tx * 4 + j];
#pragma unroll
                for (int i = 0; i < 4; i++)
#pragma unroll
                    for (int j = 0; j < 4; j++)
                        P[i][j] += a[i] * c[j];
            }
#pragma unroll
            for (int i = 0; i < 4; i++) {
                int m = m0 + ty * 4 + i;
#pragma unroll
                for (int j = 0; j < 4; j++) {
                    int kk = kt * 64 + tx * 4 + j;
                    float w = (m >= kk) ? __expf(-s * (float)(m - kk)) : 0.f;
                    Ps[(ty * 4 + i) * 65 + tx * 4 + j] = P[i][j] * w;
                }
            }
            __syncthreads();
            for (int r = 0; r < 64; r++) {
                float a[4];
#pragma unroll
                for (int i = 0; i < 4; i++) a[i] = Ps[(ty * 4 + i) * 65 + r];
                float b0[4], b1[4];
                *(float4*)b0 = *(const float4*)&vsm[r * 132 + tx * 4];
                *(float4*)b1 = *(const float4*)&vsm[r * 132 + 64 + tx * 4];
#pragma unroll
                for (int i = 0; i < 4; i++) {
#pragma unroll
                    for (int j = 0; j < 4; j++) {
                        out[i][j]     += a[i] * b0[j];
                        out[i][j + 4] += a[i] * b1[j];
                    }
                }
            }
            __syncthreads();
        }

#pragma unroll
        for (int i = 0; i < 4; i++) {
            int m = m0 + ty * 4 + i;
#pragma unroll
            for (int j = 0; j < 8; j++) {
                int e = (j < 4) ? (tx * 4 + j) : (64 + tx * 4 + j - 4);
                outp[(size_t)m * HID + e] = out[i][j];
            }
        }
        __syncthreads();
    }
}

// ---------------------------------------------------------------------------
// K4: rmsnorm * gate (verified R8)
// ---------------------------------------------------------------------------
__global__ __launch_bounds__(256)
void rms_gate(const float* __restrict__ norm_w)
{
    const int row = blockIdx.x;
    float* x        = g_attn + (size_t)row * HID;
    const float* gt = g_gate + (size_t)row * HID;

    float xv[8];
    float ss = 0.f;
#pragma unroll
    for (int p = 0; p < 8; p++) {
        xv[p] = x[threadIdx.x + p * 256];
        ss += xv[p] * xv[p];
    }
    __shared__ float red[8];
#pragma unroll
    for (int o = 16; o > 0; o >>= 1)
        ss += __shfl_xor_sync(0xffffffffu, ss, o);
    if ((threadIdx.x & 31) == 0) red[threadIdx.x >> 5] = ss;
    __syncthreads();
    float tot = 0.f;
#pragma unroll
    for (int w = 0; w < 8; w++) tot += red[w];
    float inv = rsqrtf(tot / (float)HID + 1e-6f);
#pragma unroll
    for (int p = 0; p < 8; p++) {
        int i = threadIdx.x + p * 256;
        x[i] = gt[i] * xv[p] * inv * norm_w[i];
    }
}

// ---------------------------------------------------------------------------
extern "C" void kernel_launch(void* const* d_in, const int* in_sizes, int n_in,
                              void* d_out, int out_size)
{
    const float* hidden = (const float*)d_in[0];
    const float* slope  = (const float*)d_in[1];
    const float* w_qkv  = (const float*)d_in[2];
    const float* w_gate = (const float*)d_in[3];
    const float* w_out  = (const float*)d_in[4];
    const float* norm_w = (const float*)d_in[5];
    float* out = (float*)d_out;

    cudaFuncSetAttribute(attn_S, cudaFuncAttributeMaxDynamicSharedMemorySize,
                         2 * 64 * 132 * (int)sizeof(float));
    cudaFuncSetAttribute(attn_out, cudaFuncAttributeMaxDynamicSharedMemorySize,
                         A3_SMEM_FLOATS * (int)sizeof(float));
    cudaFuncSetAttribute(gemm_wmma<0, 0>, cudaFuncAttributeMaxDynamicSharedMemorySize, GEMM_SMEM);
    cudaFuncSetAttribute(gemm_wmma<1, NQKV>, cudaFuncAttributeMaxDynamicSharedMemorySize, GEMM_SMEM);
    cudaFuncSetAttribute(gemm_wmma<2, NQKV + HID>, cudaFuncAttributeMaxDynamicSharedMemorySize, GEMM_SMEM);

    // fp32 -> bf16 hi/lo conversions
    conv_a<<<(MROWS * HID / 4 + 255) / 256, 256>>>(hidden, MROWS * HID / 4);
    conv_w<<<(NQKV * HID / 4 + 255) / 256, 256>>>(w_qkv, 0, NQKV * HID / 4);
    conv_w<<<(HID * HID / 4 + 255) / 256, 256>>>(w_gate, (size_t)NQKV * HID, HID * HID / 4);
    conv_w<<<(HID * HID / 4 + 255) / 256, 256>>>(w_out, (size_t)(NQKV + HID) * HID, HID * HID / 4);

    // 1) qkv = silu(hidden @ w_qkv^T) -> q,k,v
    gemm_wmma<0, 0><<<dim3(NQKV / 128, MROWS / 128), 256, GEMM_SMEM>>>(nullptr);
    // 2) gate = sigmoid(hidden @ w_gate^T)
    gemm_wmma<1, NQKV><<<dim3(HID / 128, MROWS / 128), 256, GEMM_SMEM>>>(nullptr);
    // 3) attention
    attn_S  <<<dim3(NB, B_ * H_), 256, 2 * 64 * 132 * sizeof(float)>>>(slope);
    attn_scan<<<(B_ * H_ * DH * DH) / 256, 256>>>(slope);
    attn_out<<<dim3(NB, B_ * H_), 256, A3_SMEM_FLOATS * sizeof(float)>>>(slope);
    // 4) rmsnorm * gate
    rms_gate<<<MROWS, 256>>>(norm_w);
    // 5) out = gated @ w_out^T
    conv_attn<<<(MROWS * HID / 4 + 255) / 256, 256>>>(MROWS * HID / 4);
    gemm_wmma<2, NQKV + HID><<<dim3(HID / 128, MROWS / 128), 256, GEMM_SMEM>>>(out);
}

// round 13
// speedup vs baseline: 1.7874x; 1.1367x over previous
#include <cuda_runtime.h>
#include <cuda_bf16.h>
#include <mma.h>
#include <cstdint>

using namespace nvcuda;

// ---------------------------------------------------------------------------
// MiniMax-M1 lightning attention — R11/R13: wmma bf16-split GEMMs with
// cp.async pipelined tile loads (R10's LDG->STS stalled on load latency every
// chunk; LDGSTS makes the copy fire-and-forget so it overlaps the MMAs).
// ---------------------------------------------------------------------------

#define B_    2
#define H_    16
#define N_    4096
#define DH    128
#define NB    16
#define BLK   256
#define HID   2048
#define MROWS (B_*N_)          // 8192
#define NQKV  (3*H_*DH)        // 6144
#define WROWS (NQKV+HID+HID)   // 10240
#define NCHUNK 96              // K'=6144 in 64-wide chunks

// Scratch (device globals; no runtime allocation allowed).
__device__ float g_q   [(size_t)B_*H_*N_*DH];
__device__ float g_k   [(size_t)B_*H_*N_*DH];
__device__ float g_v   [(size_t)B_*H_*N_*DH];
__device__ float g_attn[(size_t)MROWS*HID];
__device__ float g_gate[(size_t)MROWS*HID];
__device__ float g_S   [(size_t)B_*H_*NB*DH*DH];
__device__ float g_KV  [(size_t)B_*H_*NB*DH*DH];
__device__ __nv_bfloat16 g_Ah[(size_t)MROWS*HID];
__device__ __nv_bfloat16 g_Al[(size_t)MROWS*HID];
__device__ __nv_bfloat16 g_Wh[(size_t)WROWS*HID];
__device__ __nv_bfloat16 g_Wl[(size_t)WROWS*HID];

__device__ __forceinline__ uint32_t smem_u32(const void* p) {
    uint32_t r;
    asm("{ .reg .u64 t; cvta.to.shared.u64 t, %1; cvt.u32.u64 %0, t; }"
        : "=r"(r) : "l"(p));
    return r;
}
__device__ __forceinline__ void cp16(uint32_t dst, const void* src) {
    asm volatile("cp.async.cg.shared.global [%0], [%1], 16;" :: "r"(dst), "l"(src));
}

// ---------------------------------------------------------------------------
// fp32 -> (bf16 hi, bf16 lo) conversion kernels
// ---------------------------------------------------------------------------
__device__ __forceinline__ void cvt4(float4 v, __nv_bfloat162* hi2, __nv_bfloat162* lo2, size_t i) {
    __nv_bfloat16 h0 = __float2bfloat16(v.x), h1 = __float2bfloat16(v.y);
    __nv_bfloat16 h2 = __float2bfloat16(v.z), h3 = __float2bfloat16(v.w);
    __nv_bfloat16 l0 = __float2bfloat16(v.x - __bfloat162float(h0));
    __nv_bfloat16 l1 = __float2bfloat16(v.y - __bfloat162float(h1));
    __nv_bfloat16 l2 = __float2bfloat16(v.z - __bfloat162float(h2));
    __nv_bfloat16 l3 = __float2bfloat16(v.w - __bfloat162float(h3));
    hi2[i*2+0] = __nv_bfloat162(h0, h1); hi2[i*2+1] = __nv_bfloat162(h2, h3);
    lo2[i*2+0] = __nv_bfloat162(l0, l1); lo2[i*2+1] = __nv_bfloat162(l2, l3);
}
__global__ void conv_a(const float* __restrict__ src, int n4) {
    int i = blockIdx.x * 256 + threadIdx.x;
    if (i < n4) cvt4(((const float4*)src)[i], (__nv_bfloat162*)g_Ah, (__nv_bfloat162*)g_Al, i);
}
__global__ void conv_w(const float* __restrict__ src, size_t dst_off_elems, int n4) {
    int i = blockIdx.x * 256 + threadIdx.x;
    if (i < n4) cvt4(((const float4*)src)[i],
                     (__nv_bfloat162*)(g_Wh + dst_off_elems),
                     (__nv_bfloat162*)(g_Wl + dst_off_elems), i);
}
__global__ void conv_attn(int n4) {
    int i = blockIdx.x * 256 + threadIdx.x;
    if (i < n4) cvt4(((const float4*)g_attn)[i], (__nv_bfloat162*)g_Ah, (__nv_bfloat162*)g_Al, i);
}

// ---------------------------------------------------------------------------
// wmma bf16-split GEMM, cp.async pipelined. C[M,N] = act(A @ B^T).
// Tile 128x128, 8 warps (4x2), warp tile 32x64, BK=64, double-buffered.
// EPI: 0 silu->q/k/v scatter, 1 sigmoid->g_gate, 2 plain->Cout.
// ---------------------------------------------------------------------------
#define ASTRIDE 72
#define ABUF_ELEMS (128*ASTRIDE)            // 9216 bf16
#define BUF_BYTES  (2*ABUF_ELEMS*2)         // 36864
#define GEMM_SMEM  (2*BUF_BYTES)            // 73728

template <int EPI, int BOFFROWS>
__global__ __launch_bounds__(256, 2)
void gemm_wmma(float* __restrict__ Cout)
{
    extern __shared__ char smraw[];
    const uint32_t sb = smem_u32(smraw);

    const int tid  = threadIdx.x;
    const int wid  = tid >> 5, lane = tid & 31;
    const int wm   = wid >> 1;
    const int wn   = wid & 1;
    const int bm   = blockIdx.y * 128, bn = blockIdx.x * 128;

    const __nv_bfloat16* Bh = g_Wh + (size_t)BOFFROWS * HID;
    const __nv_bfloat16* Bl = g_Wl + (size_t)BOFFROWS * HID;

    wmma::fragment<wmma::accumulator, 16, 16, 16, float> acc[2][4];
#pragma unroll
    for (int i = 0; i < 2; i++)
#pragma unroll
        for (int j = 0; j < 4; j++) wmma::fill_fragment(acc[i][j], 0.f);

    auto load_chunk_async = [&](int c, int buf) {
        const int part = c >> 5;                  // 0:hh 1:hl 2:lh
        const int k0 = (c & 31) << 6;
        const __nv_bfloat16* As = (part < 2) ? g_Ah : g_Al;
        const __nv_bfloat16* Bs = (part == 1) ? Bl : Bh;
        const uint32_t abase = sb + buf * BUF_BYTES;
        const uint32_t bbase = abase + ABUF_ELEMS * 2;
#pragma unroll
        for (int i = 0; i < 4; i++) {
            int idx = i * 256 + tid;              // 0..1023
            int row = idx >> 3, c8 = idx & 7;     // 128 rows x 8 x 16B
            cp16(abase + (row * ASTRIDE + c8 * 8) * 2,
                 As + (size_t)(bm + row) * HID + k0 + c8 * 8);
            cp16(bbase + (row * ASTRIDE + c8 * 8) * 2,
                 Bs + (size_t)(bn + row) * HID + k0 + c8 * 8);
        }
        asm volatile("cp.async.commit_group;" ::: "memory");
    };
    auto compute = [&](int buf) {
        const __nv_bfloat16* a = (const __nv_bfloat16*)(smraw + buf * BUF_BYTES);
        const __nv_bfloat16* b = a + ABUF_ELEMS;
#pragma unroll
        for (int ks = 0; ks < 4; ks++) {
            wmma::fragment<wmma::matrix_a, 16, 16, 16, __nv_bfloat16, wmma::row_major> af[2];
            wmma::fragment<wmma::matrix_b, 16, 16, 16, __nv_bfloat16, wmma::col_major> bf[4];
#pragma unroll
            for (int i = 0; i < 2; i++)
                wmma::load_matrix_sync(af[i], a + (wm * 32 + i * 16) * ASTRIDE + ks * 16, ASTRIDE);
#pragma unroll
            for (int j = 0; j < 4; j++)
                wmma::load_matrix_sync(bf[j], b + (wn * 64 + j * 16) * ASTRIDE + ks * 16, ASTRIDE);
#pragma unroll
            for (int i = 0; i < 2; i++)
#pragma unroll
                for (int j = 0; j < 4; j++)
                    wmma::mma_sync(acc[i][j], af[i], bf[j], acc[i][j]);
        }
    };

    load_chunk_async(0, 0);
    for (int c = 0; c < NCHUNK; c++) {
        if (c + 1 < NCHUNK) {
            load_chunk_async(c + 1, (c + 1) & 1);
            asm volatile("cp.async.wait_group 1;" ::: "memory");
        } else {
            asm volatile("cp.async.wait_group 0;" ::: "memory");
        }
        __syncthreads();          // buffer c visible to all warps
        compute(c & 1);
        __syncthreads();          // all done reading before c+2 overwrites
    }

    // ---- epilogue: stage fp32 through smem (A/B buffers reused) ----
    float* stage = (float*)smraw + wid * (32 * 68);
#pragma unroll
    for (int i = 0; i < 2; i++)
#pragma unroll
        for (int j = 0; j < 4; j++)
            wmma::store_matrix_sync(stage + i * 16 * 68 + j * 16, acc[i][j], 68,
                                    wmma::mem_row_major);
    __syncwarp();

    const int mrow = bm + wm * 32 + lane;
#pragma unroll 8
    for (int c = 0; c < 64; c++) {
        float v = stage[lane * 68 + c];
        int nn = bn + wn * 64 + c;
        if (EPI == 0) {
            float sv = v / (1.f + __expf(-v));       // silu
            int s    = nn >> 11;
            int rem  = nn & 2047;
            int head = rem >> 7;
            int d    = rem & 127;
            int b    = mrow >> 12;
            int t    = mrow & 4095;
            float* dst = (s == 0) ? g_q : (s == 1) ? g_k : g_v;
            dst[(((size_t)(b * H_ + head)) * N_ + t) * DH + d] = sv;
        } else if (EPI == 1) {
            g_gate[(size_t)mrow * HID + nn] = 1.f / (1.f + __expf(-v));
        } else {
            Cout[(size_t)mrow * HID + nn] = v;
        }
    }
}

// ---------------------------------------------------------------------------
// A1: S[d][e] = sum_r k[r][d]*exp(-s*(255-r))*v[r][e]  (verified R8)
// ---------------------------------------------------------------------------
__global__ __launch_bounds__(256)
void attn_S(const float* __restrict__ slope)
{
    extern __shared__ float sm[];
    float* ks = sm;
    float* vs = sm + 64 * 132;

    const int blk = blockIdx.x;
    const int bh  = blockIdx.y;
    const float s = slope[bh & (H_ - 1)];
    const float* kp = g_k + ((size_t)bh * N_ + blk * BLK) * DH;
    const float* vp = g_v + ((size_t)bh * N_ + blk * BLK) * DH;
    const int tid = threadIdx.x, tx = tid & 15, ty = tid >> 4;

    float acc[8][8];
#pragma unroll
    for (int i = 0; i < 8; i++)
#pragma unroll
        for (int j = 0; j < 8; j++) acc[i][j] = 0.f;

    for (int c = 0; c < 4; c++) {
#pragma unroll
        for (int p = 0; p < 8; p++) {
            int idx = tid + p * 256;
            int r   = idx >> 5;
            int d   = (idx & 31) * 4;
            int rg  = c * 64 + r;
            float kd = __expf(-s * (float)(255 - rg));
            float4 k4 = *(const float4*)(kp + (size_t)rg * DH + d);
            ks[r * 132 + d + 0] = k4.x * kd;
            ks[r * 132 + d + 1] = k4.y * kd;
            ks[r * 132 + d + 2] = k4.z * kd;
            ks[r * 132 + d + 3] = k4.w * kd;
            float4 v4 = *(const float4*)(vp + (size_t)rg * DH + d);
            *(float4*)&vs[r * 132 + d] = v4;
        }
        __syncthreads();
        for (int r = 0; r < 64; r++) {
            float a[8], b[8];
            *(float4*)(a)     = *(const float4*)&ks[r * 132 + ty * 4];
            *(float4*)(a + 4) = *(const float4*)&ks[r * 132 + 64 + ty * 4];
            *(float4*)(b)     = *(const float4*)&vs[r * 132 + tx * 4];
            *(float4*)(b + 4) = *(const float4*)&vs[r * 132 + 64 + tx * 4];
#pragma unroll
            for (int i = 0; i < 8; i++)
#pragma unroll
                for (int j = 0; j < 8; j++)
                    acc[i][j] += a[i] * b[j];
        }
        __syncthreads();
    }

    float* Sp = g_S + (size_t)(bh * NB + blk) * DH * DH;
#pragma unroll
    for (int i = 0; i < 8; i++) {
        int d = (i < 4) ? (ty * 4 + i) : (64 + ty * 4 + i - 4);
#pragma unroll
        for (int j = 0; j < 8; j++) {
            int e = (j < 4) ? (tx * 4 + j) : (64 + tx * 4 + j - 4);
            Sp[d * DH + e] = acc[i][j];
        }
    }
}

// ---------------------------------------------------------------------------
// A2: parallel over bh x idx; 16-step scan per thread.
// ---------------------------------------------------------------------------
__global__ __launch_bounds__(256)
void attn_scan(const float* __restrict__ slope)
{
    int gid = blockIdx.x * 256 + threadIdx.x;
    int bh  = gid >> 14;
    int idx = gid & 16383;
    float bdec = __expf(-slope[bh & (H_ - 1)] * (float)BLK);
    const float* Sp  = g_S  + (size_t)bh * NB * DH * DH + idx;
    float*       KVp = g_KV + (size_t)bh * NB * DH * DH + idx;
    float kv = 0.f;
#pragma unroll
    for (int j = 0; j < NB; j++) {
        KVp[(size_t)j * DH * DH] = kv;
        kv = bdec * kv + Sp[(size_t)j * DH * DH];
    }
}

// ---------------------------------------------------------------------------
// A3: fused inter+intra attention output (verified R8)
// ---------------------------------------------------------------------------
#define A3_SMEM_FLOATS (128*65 + (128*65 + 64*65 + 64*132))
__global__ __launch_bounds__(256)
void attn_out(const float* __restrict__ slope)
{
    extern __shared__ float sm[];
    float* qT  = sm;
    float* un  = sm + 128 * 65;
    float* kT  = un;
    float* Ps  = un + 128 * 65;
    float* vsm = Ps + 64 * 65;
    float* kvs = un;

    const int blk = blockIdx.x;
    const int bh  = blockIdx.y;
    const float s = slope[bh & (H_ - 1)];
    const int tid = threadIdx.x, tx = tid & 15, ty = tid >> 4;

    const float* qp  = g_q  + ((size_t)bh * N_ + blk * BLK) * DH;
    const float* kp  = g_k  + ((size_t)bh * N_ + blk * BLK) * DH;
    const float* vp  = g_v  + ((size_t)bh * N_ + blk * BLK) * DH;
    const float* kvp = g_KV + (size_t)(bh * NB + blk) * DH * DH;
    const int b = bh >> 4, h = bh & (H_ - 1);
    float* outp = g_attn + ((size_t)b * N_ + blk * BLK) * HID + h * DH;

    for (int mt = 0; mt < 4; mt++) {
        const int m0 = mt * 64;
#pragma unroll
        for (int p = 0; p < 8; p++) {
            int idx = tid + p * 256;
            int r = idx >> 5;
            int d = (idx & 31) * 4;
            float4 q4 = *(const float4*)(qp + (size_t)(m0 + r) * DH + d);
            qT[(d + 0) * 65 + r] = q4.x;
            qT[(d + 1) * 65 + r] = q4.y;
            qT[(d + 2) * 65 + r] = q4.z;
            qT[(d + 3) * 65 + r] = q4.w;
        }
#pragma unroll
        for (int p = 0; p < 16; p++) {
            int idx = tid + p * 256;
            int r = idx >> 5;
            int e = (idx & 31) * 4;
            *(float4*)&kvs[r * 132 + e] = *(const float4*)(kvp + (size_t)r * DH + e);
        }
        __syncthreads();

        float out[4][8];
#pragma unroll
        for (int i = 0; i < 4; i++)
#pragma unroll
            for (int j = 0; j < 8; j++) out[i][j] = 0.f;

        for (int d = 0; d < 128; d++) {
            float a[4];
#pragma unroll
            for (int i = 0; i < 4; i++) a[i] = qT[d * 65 + ty * 4 + i];
            float b0[4], b1[4];
            *(float4*)b0 = *(const float4*)&kvs[d * 132 + tx * 4];
            *(float4*)b1 = *(const float4*)&kvs[d * 132 + 64 + tx * 4];
#pragma unroll
            for (int i = 0; i < 4; i++) {
#pragma unroll
                for (int j = 0; j < 4; j++) {
                    out[i][j]     += a[i] * b0[j];
                    out[i][j + 4] += a[i] * b1[j];
                }
            }
        }
#pragma unroll
        for (int i = 0; i < 4; i++) {
            float qd = __expf(-s * (float)(m0 + ty * 4 + i + 1));
#pragma unroll
            for (int j = 0; j < 8; j++) out[i][j] *= qd;
        }
        __syncthreads();

        for (int kt = 0; kt <= mt; kt++) {
#pragma unroll
            for (int p = 0; p < 8; p++) {
                int idx = tid + p * 256;
                int r = idx >> 5;
                int d = (idx & 31) * 4;
                float4 k4 = *(const float4*)(kp + (size_t)(kt * 64 + r) * DH + d);
                kT[(d + 0) * 65 + r] = k4.x;
                kT[(d + 1) * 65 + r] = k4.y;
                kT[(d + 2) * 65 + r] = k4.z;
                kT[(d + 3) * 65 + r] = k4.w;
                float4 v4 = *(const float4*)(vp + (size_t)(kt * 64 + r) * DH + d);
                *(float4*)&vsm[r * 132 + d] = v4;
            }
            __syncthreads();

            float P[4][4];
#pragma unroll
            for (int i = 0; i < 4; i++)
#pragma unroll
                for (int j = 0; j < 4; j++) P[i][j] = 0.f;
            for (int d = 0; d < 128; d++) {
                float a[4], c[4];
#pragma unroll
                for (int i = 0; i < 4; i++) a[i] = qT[d * 65 + ty * 4 + i];
#pragma unroll
                for (int j = 0; j < 4; j++) c[j] = kT[d * 65 + tx * 4 + j];
#pragma unroll
                for (int i = 0; i < 4; i++)
#pragma unroll
                    for (int j = 0; j < 4; j++)
                        P[i][j] += a[i] * c[j];
            }
#pragma unroll
            for (int i = 0; i < 4; i++) {
                int m = m0 + ty * 4 + i;
#pragma unroll
                for (int j = 0; j < 4; j++) {
                    int kk = kt * 64 + tx * 4 + j;
                    float w = (m >= kk) ? __expf(-s * (float)(m - kk)) : 0.f;
                    Ps[(ty * 4 + i) * 65 + tx * 4 + j] = P[i][j] * w;
                }
            }
            __syncthreads();
            for (int r = 0; r < 64; r++) {
                float a[4];
#pragma unroll
                for (int i = 0; i < 4; i++) a[i] = Ps[(ty * 4 + i) * 65 + r];
                float b0[4], b1[4];
                *(float4*)b0 = *(const float4*)&vsm[r * 132 + tx * 4];
                *(float4*)b1 = *(const float4*)&vsm[r * 132 + 64 + tx * 4];
#pragma unroll
                for (int i = 0; i < 4; i++) {
#pragma unroll
                    for (int j = 0; j < 4; j++) {
                        out[i][j]     += a[i] * b0[j];
                        out[i][j + 4] += a[i] * b1[j];
                    }
                }
            }
            __syncthreads();
        }

#pragma unroll
        for (int i = 0; i < 4; i++) {
            int m = m0 + ty * 4 + i;
#pragma unroll
            for (int j = 0; j < 8; j++) {
                int e = (j < 4) ? (tx * 4 + j) : (64 + tx * 4 + j - 4);
                outp[(size_t)m * HID + e] = out[i][j];
            }
        }
        __syncthreads();
    }
}

// ---------------------------------------------------------------------------
// K4: rmsnorm * gate (verified R8)
// ---------------------------------------------------------------------------
__global__ __launch_bounds__(256)
void rms_gate(const float* __restrict__ norm_w)
{
    const int row = blockIdx.x;
    float* x        = g_attn + (size_t)row * HID;
    const float* gt = g_gate + (size_t)row * HID;

    float xv[8];
    float ss = 0.f;
#pragma unroll
    for (int p = 0; p < 8; p++) {
        xv[p] = x[threadIdx.x + p * 256];
        ss += xv[p] * xv[p];
    }
    __shared__ float red[8];
#pragma unroll
    for (int o = 16; o > 0; o >>= 1)
        ss += __shfl_xor_sync(0xffffffffu, ss, o);
    if ((threadIdx.x & 31) == 0) red[threadIdx.x >> 5] = ss;
    __syncthreads();
    float tot = 0.f;
#pragma unroll
    for (int w = 0; w < 8; w++) tot += red[w];
    float inv = rsqrtf(tot / (float)HID + 1e-6f);
#pragma unroll
    for (int p = 0; p < 8; p++) {
        int i = threadIdx.x + p * 256;
        x[i] = gt[i] * xv[p] * inv * norm_w[i];
    }
}

// ---------------------------------------------------------------------------
extern "C" void kernel_launch(void* const* d_in, const int* in_sizes, int n_in,
                              void* d_out, int out_size)
{
    const float* hidden = (const float*)d_in[0];
    const float* slope  = (const float*)d_in[1];
    const float* w_qkv  = (const float*)d_in[2];
    const float* w_gate = (const float*)d_in[3];
    const float* w_out  = (const float*)d_in[4];
    const float* norm_w = (const float*)d_in[5];
    float* out = (float*)d_out;

    cudaFuncSetAttribute(attn_S, cudaFuncAttributeMaxDynamicSharedMemorySize,
                         2 * 64 * 132 * (int)sizeof(float));
    cudaFuncSetAttribute(attn_out, cudaFuncAttributeMaxDynamicSharedMemorySize,
                         A3_SMEM_FLOATS * (int)sizeof(float));
    cudaFuncSetAttribute(gemm_wmma<0, 0>, cudaFuncAttributeMaxDynamicSharedMemorySize, GEMM_SMEM);
    cudaFuncSetAttribute(gemm_wmma<1, NQKV>, cudaFuncAttributeMaxDynamicSharedMemorySize, GEMM_SMEM);
    cudaFuncSetAttribute(gemm_wmma<2, NQKV + HID>, cudaFuncAttributeMaxDynamicSharedMemorySize, GEMM_SMEM);

    // fp32 -> bf16 hi/lo conversions
    conv_a<<<(MROWS * HID / 4 + 255) / 256, 256>>>(hidden, MROWS * HID / 4);
    conv_w<<<(NQKV * HID / 4 + 255) / 256, 256>>>(w_qkv, 0, NQKV * HID / 4);
    conv_w<<<(HID * HID / 4 + 255) / 256, 256>>>(w_gate, (size_t)NQKV * HID, HID * HID / 4);
    conv_w<<<(HID * HID / 4 + 255) / 256, 256>>>(w_out, (size_t)(NQKV + HID) * HID, HID * HID / 4);

    // 1) qkv = silu(hidden @ w_qkv^T) -> q,k,v
    gemm_wmma<0, 0><<<dim3(NQKV / 128, MROWS / 128), 256, GEMM_SMEM>>>(nullptr);
    // 2) gate = sigmoid(hidden @ w_gate^T)
    gemm_wmma<1, NQKV><<<dim3(HID / 128, MROWS / 128), 256, GEMM_SMEM>>>(nullptr);
    // 3) attention
    attn_S  <<<dim3(NB, B_ * H_), 256, 2 * 64 * 132 * sizeof(float)>>>(slope);
    attn_scan<<<(B_ * H_ * DH * DH) / 256, 256>>>(slope);
    attn_out<<<dim3(NB, B_ * H_), 256, A3_SMEM_FLOATS * sizeof(float)>>>(slope);
    // 4) rmsnorm * gate
    rms_gate<<<MROWS, 256>>>(norm_w);
    // 5) out = gated @ w_out^T
    conv_attn<<<(MROWS * HID / 4 + 255) / 256, 256>>>(MROWS * HID / 4);
    gemm_wmma<2, NQKV + HID><<<dim3(HID / 128, MROWS / 128), 256, GEMM_SMEM>>>(out);
}